// round 11
// baseline (speedup 1.0000x reference)
#include <cuda_runtime.h>

#define N_NODES 500000
#define N_EDGES 16000000
#define FULL 0xffffffffu
#define CAP_LOG 7                              // 128 slots per node bucket
#define CAP (1 << CAP_LOG)

// ---------------- device scratch (static; no allocation) ----------------
__device__ int   g_cnt[N_NODES];               // in-degree (also fill cursor)
__device__ int   g_col[(size_t)N_NODES * CAP]; // bucketized CSR: row i at i*CAP
__device__ float g_pa[(size_t)N_NODES * 8];    // projected features (32B records)
__device__ float g_pb[(size_t)N_NODES * 8];
__device__ float g_sa[(size_t)N_NODES * 8];    // precomputed self terms
__device__ float g_sb[(size_t)N_NODES * 8];

// packed fp32x2 add (Blackwell native; ptxas never auto-fuses scalar FADDs)
__device__ __forceinline__ void addx2(unsigned long long& acc, unsigned long long v) {
    asm("add.rn.f32x2 %0, %0, %1;" : "+l"(acc) : "l"(v));
}

// ---------------- fused build: CSR fill (blocks [0,nfill)) + layer-0 proj (rest) ----------------
__global__ void __launch_bounds__(256)
k_build(const int* __restrict__ ei, int E, int nfill,
        const float* __restrict__ x,
        const float* __restrict__ Wl1, const float* __restrict__ Wr1,
        const float* __restrict__ b1,
        float* __restrict__ p0, float* __restrict__ s0) {
    if (blockIdx.x < nfill) {
        int e4 = (blockIdx.x * blockDim.x + threadIdx.x) * 4;
        if (e4 < E) {
            int4 d = *reinterpret_cast<const int4*>(ei + E + e4);  // dst
            int4 s = *reinterpret_cast<const int4*>(ei + e4);      // src
            int q0 = atomicAdd(&g_cnt[d.x], 1); g_col[((size_t)d.x << CAP_LOG) + q0] = s.x;
            int q1 = atomicAdd(&g_cnt[d.y], 1); g_col[((size_t)d.y << CAP_LOG) + q1] = s.y;
            int q2 = atomicAdd(&g_cnt[d.z], 1); g_col[((size_t)d.z << CAP_LOG) + q2] = s.z;
            int q3 = atomicAdd(&g_cnt[d.w], 1); g_col[((size_t)d.w << CAP_LOG) + q3] = s.w;
        }
        return;
    }
    // ---- layer-0 projection part ----
    __shared__ float sW[105];                 // Wl1(50) | Wr1(50) | b1(5)
    int t = threadIdx.x;
    if (t < 50)       sW[t] = Wl1[t];
    else if (t < 100) sW[t] = Wr1[t - 50];
    else if (t < 105) sW[t] = b1[t - 100];
    __syncthreads();

    int i = (blockIdx.x - nfill) * blockDim.x + t;
    if (i >= N_NODES) return;

    float xv[10];
    #pragma unroll
    for (int j = 0; j < 10; j++) xv[j] = x[(size_t)i * 10 + j];

    float pv[5], sv[5];
    #pragma unroll
    for (int d = 0; d < 5; d++) {
        float a = 0.f, bsum = sW[100 + d];
        #pragma unroll
        for (int j = 0; j < 10; j++) {
            a    = fmaf(sW[d * 10 + j],      xv[j], a);
            bsum = fmaf(sW[50 + d * 10 + j], xv[j], bsum);
        }
        pv[d] = a; sv[d] = bsum;
    }
    float4* pr = reinterpret_cast<float4*>(p0 + (size_t)i * 8);
    float4* sr = reinterpret_cast<float4*>(s0 + (size_t)i * 8);
    pr[0] = make_float4(pv[0], pv[1], pv[2], pv[3]);
    pr[1] = make_float4(pv[4], 0.f, 0.f, 0.f);
    sr[0] = make_float4(sv[0], sv[1], sv[2], sv[3]);
    sr[1] = make_float4(sv[4], 0.f, 0.f, 0.f);
}

// ---------------- fused 5-dim layer, TWO nodes per warp ----------------
// Gather at the L1tex replay floor: lane pairs load 16B halves of a node's 32B
// record (16 edges/LDG.128, 1 line/edge), 2x unrolled (4 gather LDGs in
// flight), accumulation in packed f32x2 (2 adds per 16B instead of 4 FADDs).
template<int POUT>
__global__ void __launch_bounds__(256)
k_agg5(const float* __restrict__ p, const float* __restrict__ self,
       float* __restrict__ pout, float* __restrict__ sout,
       const float* __restrict__ Wl, const float* __restrict__ Wr,
       const float* __restrict__ b) {
    __shared__ float sWl[POUT * 5], sWr[POUT * 5], sb[POUT];
    int t = threadIdx.x;
    if (t < POUT * 5)                 sWl[t]      = Wl[t];
    if (t >= 32 && t < 32 + POUT * 5) sWr[t - 32] = Wr[t - 32];
    if (t >= 64 && t < 64 + POUT)     sb[t - 64]  = b[t - 64];
    __syncthreads();

    int warp = t >> 5, lane = t & 31;
    int i0 = (blockIdx.x * (blockDim.x >> 5) + warp) * 2;
    if (i0 >= N_NODES) return;

    int2 dg = *reinterpret_cast<const int2*>(g_cnt + i0);   // degA, degB (i0 even)
    int degA = dg.x, degB = dg.y;
    int startA = i0 << CAP_LOG, startB = (i0 + 1) << CAP_LOG;
    int endA = startA + degA, endB = startB + degB;

    int half = lane & 1;                   // 0: p[0..3], 1: p[4..7]
    int epos = lane >> 1;                  // edge slot 0..15

    unsigned long long a01 = 0ull, a23 = 0ull;   // node A packed sums [d0,d1],[d2,d3]
    unsigned long long b01 = 0ull, b23 = 0ull;   // node B
    int jA = startA + epos, jB = startB + epos;
    while (jA < endA || jB < endB) {
        int sA0 = (jA      < endA) ? __ldg(g_col + jA)      : -1;
        int sA1 = (jA + 16 < endA) ? __ldg(g_col + jA + 16) : -1;
        int sB0 = (jB      < endB) ? __ldg(g_col + jB)      : -1;
        int sB1 = (jB + 16 < endB) ? __ldg(g_col + jB + 16) : -1;
        if (sA0 >= 0) {
            ulonglong2 v = __ldg(reinterpret_cast<const ulonglong2*>(p + (size_t)sA0 * 8) + half);
            addx2(a01, v.x); addx2(a23, v.y);
        }
        if (sB0 >= 0) {
            ulonglong2 v = __ldg(reinterpret_cast<const ulonglong2*>(p + (size_t)sB0 * 8) + half);
            addx2(b01, v.x); addx2(b23, v.y);
        }
        if (sA1 >= 0) {
            ulonglong2 v = __ldg(reinterpret_cast<const ulonglong2*>(p + (size_t)sA1 * 8) + half);
            addx2(a01, v.x); addx2(a23, v.y);
        }
        if (sB1 >= 0) {
            ulonglong2 v = __ldg(reinterpret_cast<const ulonglong2*>(p + (size_t)sB1 * 8) + half);
            addx2(b01, v.x); addx2(b23, v.y);
        }
        jA += 32; jB += 32;
    }

    // unpack packed sums -> float4 lanes (even lane: dims0-3; odd lane: dim4,pads)
    float4 accA, accB;
    asm("mov.b64 {%0,%1}, %2;" : "=f"(accA.x), "=f"(accA.y) : "l"(a01));
    asm("mov.b64 {%0,%1}, %2;" : "=f"(accA.z), "=f"(accA.w) : "l"(a23));
    asm("mov.b64 {%0,%1}, %2;" : "=f"(accB.x), "=f"(accB.y) : "l"(b01));
    asm("mov.b64 {%0,%1}, %2;" : "=f"(accB.z), "=f"(accB.w) : "l"(b23));

    // fold across halves (xor 16 preserves lane parity)
    accA.x += __shfl_xor_sync(FULL, accA.x, 16);
    accA.y += __shfl_xor_sync(FULL, accA.y, 16);
    accA.z += __shfl_xor_sync(FULL, accA.z, 16);
    accA.w += __shfl_xor_sync(FULL, accA.w, 16);
    accB.x += __shfl_xor_sync(FULL, accB.x, 16);
    accB.y += __shfl_xor_sync(FULL, accB.y, 16);
    accB.z += __shfl_xor_sync(FULL, accB.z, 16);
    accB.w += __shfl_xor_sync(FULL, accB.w, 16);

    int h    = lane >> 4;                  // which node this half-warp finishes
    int l16  = lane & 15;
    int base = lane & 16;
    int i    = i0 + h;
    int deg  = h ? degB : degA;

    // select this half-warp's node, then 3 parity-preserving levels
    float4 u;
    u.x = h ? accB.x : accA.x;
    u.y = h ? accB.y : accA.y;
    u.z = h ? accB.z : accA.z;
    u.w = h ? accB.w : accA.w;
    #pragma unroll
    for (int off = 2; off <= 8; off <<= 1) {
        u.x += __shfl_xor_sync(FULL, u.x, off);
        u.y += __shfl_xor_sync(FULL, u.y, off);
        u.z += __shfl_xor_sync(FULL, u.z, off);
        u.w += __shfl_xor_sync(FULL, u.w, off);
    }

    float s0 = __shfl_sync(FULL, u.x, base);         // even lane: dims0-3
    float s1 = __shfl_sync(FULL, u.y, base);
    float s2 = __shfl_sync(FULL, u.z, base);
    float s3 = __shfl_sync(FULL, u.w, base);
    float s4 = __shfl_sync(FULL, u.x, base | 1);     // odd lane: dim4

    float inv = 1.0f / (float)max(deg, 1);
    float sv  = (l16 < 5) ? __ldg(self + (size_t)i * 8 + l16) : 0.f;

    float f0 = fmaxf(fmaf(s0, inv, __shfl_sync(FULL, sv, base + 0)), 0.f);
    float f1 = fmaxf(fmaf(s1, inv, __shfl_sync(FULL, sv, base + 1)), 0.f);
    float f2 = fmaxf(fmaf(s2, inv, __shfl_sync(FULL, sv, base + 2)), 0.f);
    float f3 = fmaxf(fmaf(s3, inv, __shfl_sync(FULL, sv, base + 3)), 0.f);
    float f4 = fmaxf(fmaf(s4, inv, __shfl_sync(FULL, sv, base + 4)), 0.f);

    if (POUT == 5) {
        if (l16 < 8) {
            float w = 0.f;
            if (l16 < 5) {
                const float* r = sWl + l16 * 5;
                w = fmaf(r[0], f0, fmaf(r[1], f1, fmaf(r[2], f2, fmaf(r[3], f3, r[4] * f4))));
            }
            pout[(size_t)i * 8 + l16] = w;   // lanes 5-7 keep pads zero
        }
        if (l16 >= 8 && l16 < 13) {
            int d = l16 - 8;
            const float* r = sWr + d * 5;
            float w = fmaf(r[0], f0, fmaf(r[1], f1, fmaf(r[2], f2, fmaf(r[3], f3,
                      fmaf(r[4], f4, sb[d])))));
            sout[(size_t)i * 8 + d] = w;
        }
    } else { // POUT == 1: scalar p_next / self_next (stride 1)
        if (l16 == 0) {
            float w = fmaf(sWl[0], f0, fmaf(sWl[1], f1, fmaf(sWl[2], f2,
                      fmaf(sWl[3], f3, sWl[4] * f4))));
            pout[i] = w;
        }
        if (l16 == 1) {
            float w = fmaf(sWr[0], f0, fmaf(sWr[1], f1, fmaf(sWr[2], f2,
                      fmaf(sWr[3], f3, fmaf(sWr[4], f4, sb[0])))));
            sout[i] = w;
        }
    }
}

// ---------------- final scalar layer, two nodes per warp ----------------
__global__ void __launch_bounds__(256)
k_agg_final(const float* __restrict__ p, const float* __restrict__ self,
            float* __restrict__ out) {
    int t = threadIdx.x;
    int warp = t >> 5, lane = t & 31;
    int h = lane >> 4, l16 = lane & 15;
    int i = (blockIdx.x * (blockDim.x >> 5) + warp) * 2 + h;
    if (i - h >= N_NODES) return;

    int deg = g_cnt[i];
    int start = i << CAP_LOG, end = start + deg;
    float acc = 0.f;
    for (int j = start + l16; j < end; j += 16)
        acc += __ldg(p + __ldg(g_col + j));
    #pragma unroll
    for (int off = 1; off < 16; off <<= 1)
        acc += __shfl_xor_sync(FULL, acc, off);
    if (l16 == 0) {
        float inv = 1.0f / (float)max(deg, 1);
        out[i] = fmaf(acc, inv, __ldg(self + i));
    }
}

// ---------------- launch ----------------
extern "C" void kernel_launch(void* const* d_in, const int* in_sizes, int n_in,
                              void* d_out, int out_size) {
    const float* x    = (const float*)d_in[0];
    const int*   ei   = (const int*)  d_in[1];
    const float* Wl1  = (const float*)d_in[2];
    const float* Wr1  = (const float*)d_in[3];
    const float* b1   = (const float*)d_in[4];
    const float* Wlm  = (const float*)d_in[5];   // [8,5,5]
    const float* Wrm  = (const float*)d_in[6];   // [8,5,5]
    const float* bm   = (const float*)d_in[7];   // [8,5]
    const float* Wl10 = (const float*)d_in[8];   // [1,5]
    const float* Wr10 = (const float*)d_in[9];   // [1,5]
    const float* b10  = (const float*)d_in[10];  // [1]
    float* out = (float*)d_out;

    void *pa, *pb, *sa, *sb_, *pcnt;
    cudaGetSymbolAddress(&pa,   g_pa);
    cudaGetSymbolAddress(&pb,   g_pb);
    cudaGetSymbolAddress(&sa,   g_sa);
    cudaGetSymbolAddress(&sb_,  g_sb);
    cudaGetSymbolAddress(&pcnt, g_cnt);
    float* P[2] = { (float*)pa,  (float*)pb  };
    float* S[2] = { (float*)sa,  (float*)sb_ };

    const int E = N_EDGES;
    int e4blocks = (E / 4 + 255) / 256;      // fill blocks
    int nb       = (N_NODES + 255) / 256;    // proj blocks
    int npairs   = N_NODES / 2;
    int ablocks  = (npairs + 7) / 8;         // 2 nodes per warp, 8 warps/block

    cudaMemsetAsync(pcnt, 0, N_NODES * sizeof(int));
    k_build<<<e4blocks + nb, 256>>>(ei, E, e4blocks, x, Wl1, Wr1, b1, P[0], S[0]);

    // layers 0..7
    int cur = 0;
    for (int L = 0; L <= 7; ++L) {
        k_agg5<5><<<ablocks, 256>>>(P[cur], S[cur], P[1 - cur], S[1 - cur],
                                    Wlm + L * 25, Wrm + L * 25, bm + L * 5);
        cur = 1 - cur;
    }
    // layer 8: pre-project scalar p9/self9 with Wl10/Wr10/b10
    k_agg5<1><<<ablocks, 256>>>(P[cur], S[cur], P[1 - cur], S[1 - cur],
                                Wl10, Wr10, b10);
    cur = 1 - cur;
    // layer 9 (final, no relu): out = mean(p9) + self9
    k_agg_final<<<ablocks, 256>>>(P[cur], S[cur], out);
}